// round 1
// baseline (speedup 1.0000x reference)
#include <cuda_runtime.h>
#include <cuda_bf16.h>

// Elementwise per-column activation select.
//   out[b, n] = ACT[act_codes[n]](x[b, n]),  x: [B, N] fp32, N = C*H*W
// Codes: 0=relu, 1=sigmoid, 2=tanh, 3=elu(a=1), 4=leaky_relu(0.01), 5=gelu(tanh approx)
//
// HBM-bound: ~207 MB traffic. Strategy: float4/int4 vector loads, codes hit L2
// (1.6 MB, reused across all 64 rows), branchless select with shared
// transcendentals (1x tanh.approx + 1x ex2.approx + 1x rcp.approx per element).

__device__ __forceinline__ float f_tanh(float x) {
    float r;
    asm("tanh.approx.f32 %0, %1;" : "=f"(r) : "f"(x));
    return r;
}
__device__ __forceinline__ float f_ex2(float x) {
    float r;
    asm("ex2.approx.f32 %0, %1;" : "=f"(r) : "f"(x));
    return r;
}
__device__ __forceinline__ float f_rcp(float x) {
    float r;
    asm("rcp.approx.f32 %0, %1;" : "=f"(r) : "f"(x));
    return r;
}

__device__ __forceinline__ float apply_act(float x, int c) {
    const float LOG2E = 1.4426950408889634f;

    // Shared tanh: arg depends on code (tanh -> x, gelu -> cubic arg, else x harmless)
    float x2 = x * x;
    float g  = 0.7978845608028654f * fmaf(0.044715f * x2, x, x); // sqrt(2/pi)*(x + 0.044715 x^3)
    float ta = (c == 5) ? g : x;
    float th = f_tanh(ta);

    // Shared exp: sigmoid needs exp(-x), elu needs exp(x)
    float ea = ((c == 1) ? -x : x) * LOG2E;
    float e  = f_ex2(ea);                 // exp(+/-x)

    float sig  = f_rcp(1.0f + e);         // 1/(1+exp(-x)) ; accurate, no cancellation
    float elu  = (x > 0.0f) ? x : (e - 1.0f);
    float lrlu = (x > 0.0f) ? x : 0.01f * x;
    float gelu = 0.5f * x * (1.0f + th);

    float r;
    r = (c == 0) ? fmaxf(x, 0.0f)
      : (c == 1) ? sig
      : (c == 2) ? th
      : (c == 3) ? elu
      : (c == 4) ? lrlu
      :            gelu;
    return r;
}

// Vectorized path: N % 4 == 0. grid = (ceil(N4/256), B)
__global__ void act_select_vec4(const float4* __restrict__ x,
                                const int4*  __restrict__ codes,
                                float4* __restrict__ out,
                                int N4) {
    int n4 = blockIdx.x * blockDim.x + threadIdx.x;
    if (n4 >= N4) return;
    long long row = (long long)blockIdx.y * N4;

    float4 v = x[row + n4];
    int4   c = codes[n4];

    float4 o;
    o.x = apply_act(v.x, c.x);
    o.y = apply_act(v.y, c.y);
    o.z = apply_act(v.z, c.z);
    o.w = apply_act(v.w, c.w);

    out[row + n4] = o;
}

// Scalar fallback (any N)
__global__ void act_select_scalar(const float* __restrict__ x,
                                  const int*  __restrict__ codes,
                                  float* __restrict__ out,
                                  int N) {
    int n = blockIdx.x * blockDim.x + threadIdx.x;
    if (n >= N) return;
    long long idx = (long long)blockIdx.y * N + n;
    out[idx] = apply_act(x[idx], codes[n]);
}

extern "C" void kernel_launch(void* const* d_in, const int* in_sizes, int n_in,
                              void* d_out, int out_size) {
    const float* x     = (const float*)d_in[0];
    const int*   codes = (const int*)d_in[1];
    float*       out   = (float*)d_out;

    int N = in_sizes[1];            // C*H*W (act_codes length)
    int B = out_size / N;           // batch rows

    if ((N & 3) == 0) {
        int N4 = N >> 2;
        dim3 block(256);
        dim3 grid((N4 + 255) / 256, B);
        act_select_vec4<<<grid, block>>>((const float4*)x, (const int4*)codes,
                                         (float4*)out, N4);
    } else {
        dim3 block(256);
        dim3 grid((N + 255) / 256, B);
        act_select_scalar<<<grid, block>>>(x, codes, out, N);
    }
}

// round 2
// speedup vs baseline: 1.6674x; 1.6674x over previous
#include <cuda_runtime.h>
#include <cuda_bf16.h>

// out[b, n] = ACT[act_codes[n]](x[b, n]),  x: [B, N] fp32, N = C*H*W
// Codes: 0=relu, 1=sigmoid, 2=tanh, 3=elu(a=1), 4=leaky_relu(0.01), 5=gelu(tanh)
//
// R2 strategy: per-column codes are decoded ONCE per thread into float blend
// coefficients, then reused across ROWS rows. Per-row math is a branch-free
// FFMA chain over the basis {max(x,0), min(x,0), min(e^x-1,0), tanh, sig, x*sig}
// with 2 MUFU ops (tanh.approx, ex2.approx). sigmoid = 0.5 + 0.5*tanh(x/2).

#define ROWS 8

__device__ __forceinline__ float f_tanh(float x) {
    float r; asm("tanh.approx.f32 %0, %1;" : "=f"(r) : "f"(x)); return r;
}
__device__ __forceinline__ float f_ex2(float x) {
    float r; asm("ex2.approx.f32 %0, %1;" : "=f"(r) : "f"(x)); return r;
}

struct Coef {
    float a_xp;   // coef of max(x,0)      (relu, elu, leaky)
    float a_xn;   // coef of min(x,0)      (leaky: 0.01)
    float a_en;   // coef of min(e^x-1,0)  (elu)
    float a_th;   // coef of tanh(ta)      (tanh)
    float a_h;    // coef of 0.5+0.5*tanh  (sigmoid)
    float a_xh;   // coef of x*(0.5+0.5*tanh) (gelu)
    float targ;   // tanh-arg linear coef: 1 (tanh), 0.5 (sigmoid), 0 (gelu)
    float gw;     // tanh-arg cubic coef: 1 (gelu), 0 else
};

__device__ __forceinline__ Coef make_coef(int c) {
    Coef k;
    k.a_xp = (c == 0 || c == 3 || c == 4) ? 1.0f : 0.0f;
    k.a_xn = (c == 4) ? 0.01f : 0.0f;
    k.a_en = (c == 3) ? 1.0f : 0.0f;
    k.a_th = (c == 2) ? 1.0f : 0.0f;
    k.a_h  = (c == 1) ? 1.0f : 0.0f;
    k.a_xh = (c == 5) ? 1.0f : 0.0f;
    k.targ = (c == 5) ? 0.0f : ((c == 1) ? 0.5f : 1.0f);
    k.gw   = (c == 5) ? 1.0f : 0.0f;
    return k;
}

__device__ __forceinline__ float act(float x, const Coef& k) {
    const float LOG2E = 1.4426950408889634f;
    float xp = fmaxf(x, 0.0f);
    float xn = fminf(x, 0.0f);
    float e  = f_ex2(x * LOG2E);                 // exp(x)
    float en = fminf(e - 1.0f, 0.0f);            // elu negative part
    float x2 = x * x;
    float g  = 0.7978845608028654f * fmaf(0.044715f * x2, x, x);
    float ta = fmaf(k.targ, x, k.gw * g);        // tanh argument
    float th = f_tanh(ta);
    float h  = fmaf(0.5f, th, 0.5f);             // sigmoid (if ta = x/2)
    float r  = k.a_xp * xp;
    r = fmaf(k.a_xn, xn, r);
    r = fmaf(k.a_en, en, r);
    r = fmaf(k.a_th, th, r);
    r = fmaf(k.a_h,  h,  r);
    r = fmaf(k.a_xh, x * h, r);
    return r;
}

// Vectorized: one thread = one float4 column group, ROWS rows.
__global__ void __launch_bounds__(256) act_select_vec4_rows(
    const float4* __restrict__ x,
    const int4*  __restrict__ codes,
    float4* __restrict__ out,
    int N4) {
    int n4 = blockIdx.x * blockDim.x + threadIdx.x;
    if (n4 >= N4) return;

    int4 c = codes[n4];
    Coef k0 = make_coef(c.x);
    Coef k1 = make_coef(c.y);
    Coef k2 = make_coef(c.z);
    Coef k3 = make_coef(c.w);

    size_t base = (size_t)blockIdx.y * ROWS * N4 + n4;

#pragma unroll
    for (int rr = 0; rr < ROWS; rr += 4) {
        float4 v[4];
#pragma unroll
        for (int i = 0; i < 4; i++)
            v[i] = x[base + (size_t)(rr + i) * N4];
#pragma unroll
        for (int i = 0; i < 4; i++) {
            float4 o;
            o.x = act(v[i].x, k0);
            o.y = act(v[i].y, k1);
            o.z = act(v[i].z, k2);
            o.w = act(v[i].w, k3);
            out[base + (size_t)(rr + i) * N4] = o;
        }
    }
}

// Generic scalar fallback (any N, any B)
__global__ void act_select_scalar(const float* __restrict__ x,
                                  const int*  __restrict__ codes,
                                  float* __restrict__ out,
                                  int N) {
    int n = blockIdx.x * blockDim.x + threadIdx.x;
    if (n >= N) return;
    Coef k = make_coef(codes[n]);
    size_t idx = (size_t)blockIdx.y * N + n;
    out[idx] = act(x[idx], k);
}

extern "C" void kernel_launch(void* const* d_in, const int* in_sizes, int n_in,
                              void* d_out, int out_size) {
    const float* x     = (const float*)d_in[0];
    const int*   codes = (const int*)d_in[1];
    float*       out   = (float*)d_out;

    int N = in_sizes[1];            // C*H*W
    int B = out_size / N;

    if ((N & 3) == 0 && (B % ROWS) == 0) {
        int N4 = N >> 2;
        dim3 block(256);
        dim3 grid((N4 + 255) / 256, B / ROWS);
        act_select_vec4_rows<<<grid, block>>>((const float4*)x, (const int4*)codes,
                                              (float4*)out, N4);
    } else {
        dim3 block(256);
        dim3 grid((N + 255) / 256, B);
        act_select_scalar<<<grid, block>>>(x, codes, out, N);
    }
}

// round 4
// speedup vs baseline: 1.7442x; 1.0461x over previous
#include <cuda_runtime.h>
#include <cuda_bf16.h>

// out[b, n] = ACT[act_codes[n]](x[b, n]),  x: [B, N] fp32, N = C*H*W
// Codes: 0=relu, 1=sigmoid, 2=tanh, 3=elu(a=1), 4=leaky_relu(0.01), 5=gelu(tanh)
//
// R3: packed f32x2 arithmetic (fma.rn.f32x2 et al., sm_103a) over basis
//   { x+|x|, x-|x|, min(e^x,1), (m*x+b)*tanh(ta), 1 }
// with per-column coefficients decoded once per thread and reused over 16 rows.
// Only tanh/ex2 (MUFU) and the min(e,1) clamp run scalar.

typedef unsigned long long u64;

__device__ __forceinline__ float f_tanh(float x) {
    float r; asm("tanh.approx.f32 %0, %1;" : "=f"(r) : "f"(x)); return r;
}
__device__ __forceinline__ float f_ex2(float x) {
    float r; asm("ex2.approx.f32 %0, %1;" : "=f"(r) : "f"(x)); return r;
}

__device__ __forceinline__ u64 pk(float lo, float hi) {
    u64 r; asm("mov.b64 %0, {%1, %2};" : "=l"(r) : "f"(lo), "f"(hi)); return r;
}
__device__ __forceinline__ float2 upk(u64 v) {
    float2 f; asm("mov.b64 {%0, %1}, %2;" : "=f"(f.x), "=f"(f.y) : "l"(v)); return f;
}
__device__ __forceinline__ u64 f2fma(u64 a, u64 b, u64 c) {
    u64 d; asm("fma.rn.f32x2 %0, %1, %2, %3;" : "=l"(d) : "l"(a), "l"(b), "l"(c)); return d;
}
__device__ __forceinline__ u64 f2mul(u64 a, u64 b) {
    u64 d; asm("mul.rn.f32x2 %0, %1, %2;" : "=l"(d) : "l"(a), "l"(b)); return d;
}
__device__ __forceinline__ u64 f2add(u64 a, u64 b) {
    u64 d; asm("add.rn.f32x2 %0, %1, %2;" : "=l"(d) : "l"(a), "l"(b)); return d;
}

#define ROWS 16

// ---- per-code scalar coefficients --------------------------------------
struct CoefS { float axp, axn, aen, ac, m, b, cl, cq; };

__device__ __forceinline__ CoefS make_coef(int c) {
    CoefS k;
    // coef of (x+|x|)
    k.axp = (c == 0 || c == 3 || c == 4) ? 0.5f : ((c == 5) ? 0.25f : 0.0f);
    // coef of (x-|x|)
    k.axn = (c == 4) ? 0.005f : ((c == 5) ? 0.25f : 0.0f);
    // coef of min(e^x, 1)
    k.aen = (c == 3) ? 1.0f : 0.0f;
    // constant
    k.ac  = (c == 1) ? 0.5f : ((c == 3) ? -1.0f : 0.0f);
    // tanh blend: r += (m*x + b) * tanh(ta)
    k.m   = (c == 5) ? 0.5f : 0.0f;
    k.b   = (c == 2) ? 1.0f : ((c == 1) ? 0.5f : 0.0f);
    // tanh arg: ta = x * (cl + cq*x^2)
    k.cl  = (c == 2) ? 1.0f : ((c == 1) ? 0.5f : ((c == 5) ? 0.7978845608028654f : 0.0f));
    k.cq  = (c == 5) ? 0.0356774081363001f : 0.0f;
    return k;
}

// packed (two columns) coefficients
struct CoefP { u64 axp, axn, aen, ac, m, b, cl, cq; };

__device__ __forceinline__ CoefP pack_coef(const CoefS& a, const CoefS& b2) {
    CoefP p;
    p.axp = pk(a.axp, b2.axp);  p.axn = pk(a.axn, b2.axn);
    p.aen = pk(a.aen, b2.aen);  p.ac  = pk(a.ac,  b2.ac);
    p.m   = pk(a.m,   b2.m);    p.b   = pk(a.b,   b2.b);
    p.cl  = pk(a.cl,  b2.cl);   p.cq  = pk(a.cq,  b2.cq);
    return p;
}

__device__ __forceinline__ u64 act2(u64 xv, const CoefP& k) {
    const u64 ABS  = 0x7FFFFFFF7FFFFFFFULL;
    const u64 NEG1 = 0xBF800000BF800000ULL;  // (-1, -1)
    const u64 L2E  = 0x3FB8AA3B3FB8AA3BULL;  // (log2e, log2e)

    u64 ax  = xv & ABS;
    u64 xpb = f2add(xv, ax);            // x + |x|
    u64 xnb = f2fma(ax, NEG1, xv);      // x - |x|
    u64 x2  = f2mul(xv, xv);
    u64 q   = f2fma(k.cq, x2, k.cl);
    u64 ta  = f2mul(q, xv);             // tanh argument
    u64 em  = f2mul(xv, L2E);           // x * log2(e)

    float2 taf = upk(ta);
    float2 emf = upk(em);
    float th0 = f_tanh(taf.x);
    float th1 = f_tanh(taf.y);
    float en0 = fminf(f_ex2(emf.x), 1.0f);
    float en1 = fminf(f_ex2(emf.y), 1.0f);
    u64 th = pk(th0, th1);
    u64 en = pk(en0, en1);

    u64 t = f2fma(k.m, xv, k.b);
    u64 r = f2fma(k.axp, xpb, k.ac);
    r = f2fma(k.axn, xnb, r);
    r = f2fma(k.aen, en,  r);
    r = f2fma(t,     th,  r);
    return r;
}

// One thread = one float4 column group (2 packed pairs), ROWS rows.
__global__ void __launch_bounds__(256) act_select_p2(
    const ulonglong2* __restrict__ x,
    const int4*  __restrict__ codes,
    ulonglong2* __restrict__ out,
    int N4) {
    int n4 = blockIdx.x * blockDim.x + threadIdx.x;
    if (n4 >= N4) return;

    int4 c = codes[n4];
    CoefP kA = pack_coef(make_coef(c.x), make_coef(c.y));
    CoefP kB = pack_coef(make_coef(c.z), make_coef(c.w));

    size_t base = (size_t)blockIdx.y * ROWS * N4 + n4;

#pragma unroll
    for (int rr = 0; rr < ROWS; rr += 4) {
        ulonglong2 v[4];
#pragma unroll
        for (int i = 0; i < 4; i++)
            v[i] = x[base + (size_t)(rr + i) * N4];
#pragma unroll
        for (int i = 0; i < 4; i++) {
            ulonglong2 o;
            o.x = act2(v[i].x, kA);
            o.y = act2(v[i].y, kB);
            out[base + (size_t)(rr + i) * N4] = o;
        }
    }
}

// ---- generic scalar fallback -------------------------------------------
__device__ __forceinline__ float act1(float x, const CoefS& k) {
    float ax  = fabsf(x);
    float xpb = x + ax;
    float xnb = x - ax;
    float ta  = x * fmaf(k.cq, x * x, k.cl);
    float en  = fminf(f_ex2(x * 1.4426950408889634f), 1.0f);
    float th  = f_tanh(ta);
    float t   = fmaf(k.m, x, k.b);
    float r   = fmaf(k.axp, xpb, k.ac);
    r = fmaf(k.axn, xnb, r);
    r = fmaf(k.aen, en,  r);
    r = fmaf(t,     th,  r);
    return r;
}

__global__ void act_select_scalar(const float* __restrict__ x,
                                  const int*  __restrict__ codes,
                                  float* __restrict__ out,
                                  int N) {
    int n = blockIdx.x * blockDim.x + threadIdx.x;
    if (n >= N) return;
    CoefS k = make_coef(codes[n]);
    size_t idx = (size_t)blockIdx.y * N + n;
    out[idx] = act1(x[idx], k);
}

extern "C" void kernel_launch(void* const* d_in, const int* in_sizes, int n_in,
                              void* d_out, int out_size) {
    const float* x     = (const float*)d_in[0];
    const int*   codes = (const int*)d_in[1];
    float*       out   = (float*)d_out;

    int N = in_sizes[1];            // C*H*W
    int B = out_size / N;

    if ((N & 3) == 0 && (B % ROWS) == 0) {
        int N4 = N >> 2;
        dim3 block(256);
        dim3 grid((N4 + 255) / 256, B / ROWS);
        act_select_p2<<<grid, block>>>((const ulonglong2*)x, (const int4*)codes,
                                       (ulonglong2*)out, N4);
    } else {
        dim3 block(256);
        dim3 grid((N + 255) / 256, B);
        act_select_scalar<<<grid, block>>>(x, codes, out, N);
    }
}

// round 5
// speedup vs baseline: 1.7753x; 1.0179x over previous
#include <cuda_runtime.h>
#include <cuda_bf16.h>

// out[b, n] = ACT[act_codes[n]](x[b, n]),  x: [B, N] fp32, N = C*H*W
// Codes: 0=relu, 1=sigmoid, 2=tanh, 3=elu(a=1), 4=leaky_relu(0.01), 5=gelu(tanh)
//
// R5: latency-bound fix. One thread = one u64 (2 columns) so the packed
// coefficient block is 16 regs (was 32), ROWS=8 loads front-batched (MLP=8),
// __launch_bounds__(256,5) -> 40 warps/SM. Packed f32x2 blend math unchanged.

typedef unsigned long long u64;

__device__ __forceinline__ float f_tanh(float x) {
    float r; asm("tanh.approx.f32 %0, %1;" : "=f"(r) : "f"(x)); return r;
}
__device__ __forceinline__ float f_ex2(float x) {
    float r; asm("ex2.approx.f32 %0, %1;" : "=f"(r) : "f"(x)); return r;
}

__device__ __forceinline__ u64 pk(float lo, float hi) {
    u64 r; asm("mov.b64 %0, {%1, %2};" : "=l"(r) : "f"(lo), "f"(hi)); return r;
}
__device__ __forceinline__ float2 upk(u64 v) {
    float2 f; asm("mov.b64 {%0, %1}, %2;" : "=f"(f.x), "=f"(f.y) : "l"(v)); return f;
}
__device__ __forceinline__ u64 f2fma(u64 a, u64 b, u64 c) {
    u64 d; asm("fma.rn.f32x2 %0, %1, %2, %3;" : "=l"(d) : "l"(a), "l"(b), "l"(c)); return d;
}
__device__ __forceinline__ u64 f2mul(u64 a, u64 b) {
    u64 d; asm("mul.rn.f32x2 %0, %1, %2;" : "=l"(d) : "l"(a), "l"(b)); return d;
}
__device__ __forceinline__ u64 f2add(u64 a, u64 b) {
    u64 d; asm("add.rn.f32x2 %0, %1, %2;" : "=l"(d) : "l"(a), "l"(b)); return d;
}

#define ROWS 8

// ---- per-code scalar coefficients --------------------------------------
struct CoefS { float axp, axn, aen, ac, m, b, cl, cq; };

__device__ __forceinline__ CoefS make_coef(int c) {
    CoefS k;
    k.axp = (c == 0 || c == 3 || c == 4) ? 0.5f : ((c == 5) ? 0.25f : 0.0f);
    k.axn = (c == 4) ? 0.005f : ((c == 5) ? 0.25f : 0.0f);
    k.aen = (c == 3) ? 1.0f : 0.0f;
    k.ac  = (c == 1) ? 0.5f : ((c == 3) ? -1.0f : 0.0f);
    k.m   = (c == 5) ? 0.5f : 0.0f;
    k.b   = (c == 2) ? 1.0f : ((c == 1) ? 0.5f : 0.0f);
    k.cl  = (c == 2) ? 1.0f : ((c == 1) ? 0.5f : ((c == 5) ? 0.7978845608028654f : 0.0f));
    k.cq  = (c == 5) ? 0.0356774081363001f : 0.0f;
    return k;
}

// packed (two columns) coefficients: 8 u64 = 16 regs
struct CoefP { u64 axp, axn, aen, ac, m, b, cl, cq; };

__device__ __forceinline__ CoefP pack_coef(const CoefS& a, const CoefS& b2) {
    CoefP p;
    p.axp = pk(a.axp, b2.axp);  p.axn = pk(a.axn, b2.axn);
    p.aen = pk(a.aen, b2.aen);  p.ac  = pk(a.ac,  b2.ac);
    p.m   = pk(a.m,   b2.m);    p.b   = pk(a.b,   b2.b);
    p.cl  = pk(a.cl,  b2.cl);   p.cq  = pk(a.cq,  b2.cq);
    return p;
}

__device__ __forceinline__ u64 act2(u64 xv, const CoefP& k) {
    const u64 ABS  = 0x7FFFFFFF7FFFFFFFULL;
    const u64 NEG1 = 0xBF800000BF800000ULL;  // (-1, -1)
    const u64 L2E  = 0x3FB8AA3B3FB8AA3BULL;  // (log2e, log2e)

    u64 ax  = xv & ABS;
    u64 xpb = f2add(xv, ax);            // x + |x|
    u64 xnb = f2fma(ax, NEG1, xv);      // x - |x|
    u64 x2  = f2mul(xv, xv);
    u64 q   = f2fma(k.cq, x2, k.cl);
    u64 ta  = f2mul(q, xv);             // tanh argument
    u64 em  = f2mul(xv, L2E);           // x * log2(e)

    float2 taf = upk(ta);
    float2 emf = upk(em);
    float th0 = f_tanh(taf.x);
    float th1 = f_tanh(taf.y);
    float en0 = fminf(f_ex2(emf.x), 1.0f);
    float en1 = fminf(f_ex2(emf.y), 1.0f);
    u64 th = pk(th0, th1);
    u64 en = pk(en0, en1);

    u64 t = f2fma(k.m, xv, k.b);
    u64 r = f2fma(k.axp, xpb, k.ac);
    r = f2fma(k.axn, xnb, r);
    r = f2fma(k.aen, en,  r);
    r = f2fma(t,     th,  r);
    return r;
}

// One thread = one u64 column pair, ROWS rows, loads front-batched.
__global__ void __launch_bounds__(256, 5) act_select_u64(
    const u64* __restrict__ x,
    const int2* __restrict__ codes,
    u64* __restrict__ out,
    int N2) {
    int n2 = blockIdx.x * blockDim.x + threadIdx.x;
    if (n2 >= N2) return;

    int2 c = codes[n2];
    CoefP k = pack_coef(make_coef(c.x), make_coef(c.y));

    size_t base = (size_t)blockIdx.y * ROWS * N2 + n2;

    u64 v[ROWS];
#pragma unroll
    for (int i = 0; i < ROWS; i++)
        v[i] = x[base + (size_t)i * N2];

#pragma unroll
    for (int i = 0; i < ROWS; i++)
        out[base + (size_t)i * N2] = act2(v[i], k);
}

// ---- generic scalar fallback -------------------------------------------
__device__ __forceinline__ float act1(float x, const CoefS& k) {
    float ax  = fabsf(x);
    float xpb = x + ax;
    float xnb = x - ax;
    float ta  = x * fmaf(k.cq, x * x, k.cl);
    float en  = fminf(f_ex2(x * 1.4426950408889634f), 1.0f);
    float th  = f_tanh(ta);
    float t   = fmaf(k.m, x, k.b);
    float r   = fmaf(k.axp, xpb, k.ac);
    r = fmaf(k.axn, xnb, r);
    r = fmaf(k.aen, en,  r);
    r = fmaf(t,     th,  r);
    return r;
}

__global__ void act_select_scalar(const float* __restrict__ x,
                                  const int*  __restrict__ codes,
                                  float* __restrict__ out,
                                  int N) {
    int n = blockIdx.x * blockDim.x + threadIdx.x;
    if (n >= N) return;
    CoefS k = make_coef(codes[n]);
    size_t idx = (size_t)blockIdx.y * N + n;
    out[idx] = act1(x[idx], k);
}

extern "C" void kernel_launch(void* const* d_in, const int* in_sizes, int n_in,
                              void* d_out, int out_size) {
    const float* x     = (const float*)d_in[0];
    const int*   codes = (const int*)d_in[1];
    float*       out   = (float*)d_out;

    int N = in_sizes[1];            // C*H*W
    int B = out_size / N;

    if ((N & 1) == 0 && (B % ROWS) == 0) {
        int N2 = N >> 1;
        dim3 block(256);
        dim3 grid((N2 + 255) / 256, B / ROWS);
        act_select_u64<<<grid, block>>>((const u64*)x, (const int2*)codes,
                                        (u64*)out, N2);
    } else {
        dim3 block(256);
        dim3 grid((N + 255) / 256, B);
        act_select_scalar<<<grid, block>>>(x, codes, out, N);
    }
}